// round 13
// baseline (speedup 1.0000x reference)
#include <cuda_runtime.h>
#include <cuda_fp16.h>
#include <cstdint>

// ============================================================
// out[8192,4096] = x[8192,4096] @ sign(W)[4096,4096]^T + sign(b)
// Base-PTX tensor path: cp.async + ldmatrix + mma.sync.m16n8k16.f32.f16.
// R13: warp-specialized producer. 288 thr, 1 CTA/SM: 8 consumer warps
//      (2m x 4n, 64x64 tiles, BM=128 BN=256) + 1 producer warp owning all
//      cp.asyncs into a 4-stage ring. Consumers sync only via try_wait on
//      HW full-barriers + per-warp empty arrives -> no warp convergence.
// ============================================================

static constexpr int M = 8192;
static constexpr int N = 4096;
static constexpr int K = 4096;

static constexpr int BM = 128;
static constexpr int BN = 256;
static constexpr int BK = 64;
static constexpr int KT = K / BK;          // 64 k-tiles
static constexpr int STAGES = 4;
static constexpr int NTHREADS = 288;       // 8 consumer warps + 1 producer

static constexpr int ROW_HALFS = BK + 8;   // 72 halves = 144B row (9x16B, conflict-free)
static constexpr int ROW_BYTES = ROW_HALFS * 2;              // 144
static constexpr int A_TILE_BYTES = BM * ROW_BYTES;          // 18432
static constexpr int B_TILE_BYTES = BN * ROW_BYTES;          // 36864
static constexpr int STAGE_BYTES = A_TILE_BYTES + B_TILE_BYTES; // 55296
static constexpr int SMEM_DATA = 1024;                       // barriers below
static constexpr int SMEM_TOTAL = SMEM_DATA + STAGES * STAGE_BYTES; // 222208

// ---------------- scratch (__device__ globals: alloc-free rule) ------------
__device__ __half g_xh[(size_t)M * K];   // fp16(x)
__device__ __half g_wh[(size_t)N * K];   // fp16(sign(W))
__device__ float  g_bs[N];               // sign(bias)

// ---------------- PTX helpers -----------------------------------------------
__device__ __forceinline__ uint32_t smem_u32(const void* p) {
    uint32_t a;
    asm("{ .reg .u64 t; cvta.to.shared.u64 t, %1; cvt.u32.u64 %0, t; }"
        : "=r"(a) : "l"(p));
    return a;
}

__device__ __forceinline__ void cp16(uint32_t s, const void* g) {
    asm volatile("cp.async.cg.shared.global [%0], [%1], 16;"
                 :: "r"(s), "l"(g) : "memory");
}

#define MBAR_INIT(a, c) \
    asm volatile("mbarrier.init.shared.b64 [%0], %1;" :: "r"(a), "r"((uint32_t)(c)) : "memory")
#define MBAR_ARRIVE(a) \
    asm volatile("mbarrier.arrive.shared.b64 _, [%0];" :: "r"(a) : "memory")
// arrive on mbarrier when all of this thread's prior cp.asyncs complete
#define CP_MBAR_ARRIVE(a) \
    asm volatile("cp.async.mbarrier.arrive.noinc.shared.b64 [%0];" :: "r"(a) : "memory")

#define MBAR_WAIT(a, ph) do {                                               \
    uint32_t _m = (a); uint32_t _p = (ph); uint32_t _d;                     \
    asm volatile("{ .reg .pred p;"                                          \
        " mbarrier.try_wait.parity.shared.b64 p, [%1], %2;"                 \
        " selp.b32 %0, 1, 0, p; }" : "=r"(_d) : "r"(_m), "r"(_p) : "memory");\
    if (!_d) {                                                              \
        asm volatile("{ .reg .pred P1;"                                     \
            " WL_%=: mbarrier.try_wait.parity.shared.b64 P1, [%0], %1, 0x989680;"\
            " @P1 bra.uni WD_%=; bra.uni WL_%=; WD_%=: }"                   \
            :: "r"(_m), "r"(_p) : "memory");                                \
    } } while (0)

__device__ __forceinline__ void ldsm4(uint32_t* r, uint32_t addr) {
    asm volatile("ldmatrix.sync.aligned.m8n8.x4.shared.b16 {%0,%1,%2,%3}, [%4];"
                 : "=r"(r[0]), "=r"(r[1]), "=r"(r[2]), "=r"(r[3]) : "r"(addr));
}

__device__ __forceinline__ void mma16816(float* c, const uint32_t* a,
                                         uint32_t b0, uint32_t b1) {
    asm volatile(
        "mma.sync.aligned.m16n8k16.row.col.f32.f16.f16.f32 "
        "{%0,%1,%2,%3}, {%4,%5,%6,%7}, {%8,%9}, {%0,%1,%2,%3};"
        : "+f"(c[0]), "+f"(c[1]), "+f"(c[2]), "+f"(c[3])
        : "r"(a[0]), "r"(a[1]), "r"(a[2]), "r"(a[3]), "r"(b0), "r"(b1));
}

// ---------------- prep: fp32 -> fp16 / sign ---------------------------------
__device__ __forceinline__ float fsign(float v) {
    return (v > 0.f) ? 1.f : ((v < 0.f) ? -1.f : 0.f);
}

__global__ void prep_kernel(const float* __restrict__ x,
                            const float* __restrict__ w,
                            const float* __restrict__ b) {
    const long tid = (long)blockIdx.x * blockDim.x + threadIdx.x;
    const long stride = (long)gridDim.x * blockDim.x;
    const long NX4 = ((long)M * K) / 4;
    const long NW4 = ((long)N * K) / 4;

    __half2* xh2 = reinterpret_cast<__half2*>(g_xh);
    __half2* wh2 = reinterpret_cast<__half2*>(g_wh);

    for (long t = tid; t < NX4; t += stride) {
        float4 v = reinterpret_cast<const float4*>(x)[t];
        xh2[2 * t + 0] = __floats2half2_rn(v.x, v.y);
        xh2[2 * t + 1] = __floats2half2_rn(v.z, v.w);
    }
    for (long t = tid; t < NW4; t += stride) {
        float4 v = reinterpret_cast<const float4*>(w)[t];
        wh2[2 * t + 0] = __floats2half2_rn(fsign(v.x), fsign(v.y));
        wh2[2 * t + 1] = __floats2half2_rn(fsign(v.z), fsign(v.w));
    }
    if (tid < N) g_bs[tid] = fsign(b[tid]);
}

// ---------------- GEMM -------------------------------------------------------
// grid (N/BN=16, M/BM=64). Warps 0-7 consume (2m x 4n, 64x64 each);
// warp 8 produces all cp.asyncs into a 4-stage ring.
// full[s]: count=32 (producer HW arrivals). empty[s]: count=8 (consumer warps).
__global__ void __launch_bounds__(NTHREADS, 1)
gemm_kernel(float* __restrict__ out) {
    extern __shared__ __half smem[];
    const uint32_t sbase = smem_u32(smem);

    const int tid = threadIdx.x;
    const int wid = tid >> 5;
    const int lane = tid & 31;

    const int bn = blockIdx.x;          // 0..15
    const int bm = blockIdx.y;          // 0..63
    const int bid = bm * gridDim.x + bn;
    const int phase = (bid & 3) * (KT / 4);   // spread L2 k-streams

    auto full_bar  = [&](int s) { return sbase + (uint32_t)s * 16; };
    auto empty_bar = [&](int s) { return sbase + (uint32_t)s * 16 + 8; };

    if (tid == 0) {
        #pragma unroll
        for (int s = 0; s < STAGES; s++) {
            MBAR_INIT(full_bar(s), 32);   // producer warp HW arrivals
            MBAR_INIT(empty_bar(s), 8);   // one arrive per consumer warp
        }
    }
    __syncthreads();

    if (wid == 8) {
        // ======================= PRODUCER WARP ==============================
        // lane -> (base row = lane>>3, 16B chunk kc = lane&7); rows step by 4.
        const int p_r = lane >> 3;
        const int p_kc = lane & 7;
        const __half* pA = g_xh + (size_t)(bm * BM + p_r) * K + p_kc * 8;
        const __half* pB = g_wh + (size_t)(bn * BN + p_r) * K + p_kc * 8;
        const uint32_t s_off = SMEM_DATA + p_r * ROW_BYTES + p_kc * 16;

        for (int s = 0; s < KT; s++) {
            if (s >= STAGES)
                MBAR_WAIT(empty_bar(s & 3), ((s - STAGES) >> 2) & 1);
            const int kt = (s + phase) & (KT - 1);
            const uint32_t sA = sbase + s_off + (s & 3) * STAGE_BYTES;
            const uint32_t sB = sA + A_TILE_BYTES;
            const __half* gA = pA + (size_t)kt * BK;
            const __half* gB = pB + (size_t)kt * BK;
            #pragma unroll
            for (int i = 0; i < 32; i++)           // A: 128 rows
                cp16(sA + i * (4 * ROW_BYTES), gA + (size_t)(i * 4) * K);
            #pragma unroll
            for (int i = 0; i < 64; i++)           // B: 256 rows
                cp16(sB + i * (4 * ROW_BYTES), gB + (size_t)(i * 4) * K);
            CP_MBAR_ARRIVE(full_bar(s & 3));       // fires when lane's cps land
        }
        return;  // producer skips epilogue
    }

    // ========================= CONSUMER WARPS ================================
    const int warp_m = wid & 1;         // 0..1
    const int warp_n = wid >> 1;        // 0..3

    const int rowA = warp_m * 64 + (lane & 15);
    const int kbA  = (lane >> 4) * 8;                        // halves
    const int rowB = warp_n * 64 + (lane & 7) + (lane >> 4) * 8;
    const int kbB  = ((lane >> 3) & 1) * 8;                  // halves

    float acc[4][8][4];
    #pragma unroll
    for (int i = 0; i < 4; i++)
        #pragma unroll
        for (int j = 0; j < 8; j++)
            #pragma unroll
            for (int e = 0; e < 4; e++) acc[i][j][e] = 0.f;

    auto load_frags = [&](int stage, int kk, uint32_t (*a)[4], uint32_t (*b)[4]) {
        const uint32_t sA = sbase + SMEM_DATA + stage * STAGE_BYTES;
        const uint32_t sB = sA + A_TILE_BYTES;
        #pragma unroll
        for (int im = 0; im < 4; im++)
            ldsm4(a[im], sA + (rowA + im * 16) * ROW_BYTES + (kbA + kk * 16) * 2);
        #pragma unroll
        for (int q = 0; q < 4; q++)
            ldsm4(b[q], sB + (rowB + q * 16) * ROW_BYTES + (kbB + kk * 16) * 2);
    };

    auto mma_half = [&](uint32_t (*a)[4], uint32_t (*b)[4]) {
        #pragma unroll
        for (int im = 0; im < 4; im++)
            #pragma unroll
            for (int jn = 0; jn < 8; jn++)
                mma16816(acc[im][jn],
                         a[im], b[jn >> 1][(jn & 1) * 2],
                                b[jn >> 1][(jn & 1) * 2 + 1]);
    };

    uint32_t a0[4][4], b0[4][4], a1[4][4], b1[4][4];

    MBAR_WAIT(full_bar(0), 0);           // stage 0 resident (32 HW arrivals)
    load_frags(0, 0, a0, b0);

    for (int j = 0; j < KT; j++) {
        const int b = j & 3;

        load_frags(b, 1, a1, b1);
        mma_half(a0, b0);                   // kk=0
        load_frags(b, 2, a0, b0);
        mma_half(a1, b1);                   // kk=1
        load_frags(b, 3, a1, b1);
        mma_half(a0, b0);                   // kk=2

        if (j + 1 < KT) {
            MBAR_WAIT(full_bar((j + 1) & 3), ((j + 1) >> 2) & 1);
            load_frags((j + 1) & 3, 0, a0, b0);
        }
        mma_half(a1, b1);                   // kk=3 consumes stage j's last frags

        if (lane == 0) MBAR_ARRIVE(empty_bar(b));  // this warp done with stage j
    }

    // ---------------- epilogue: add sign(bias), store fp32 ------------------
    const int col0 = bn * BN + warp_n * 64 + 2 * (lane & 3);
    const int row0 = bm * BM + warp_m * 64 + (lane >> 2);
    #pragma unroll
    for (int jn = 0; jn < 8; jn++) {
        const int c = col0 + jn * 8;
        const float b0v = g_bs[c];
        const float b1v = g_bs[c + 1];
        #pragma unroll
        for (int im = 0; im < 4; im++) {
            const int r = row0 + im * 16;
            float2 v0 = make_float2(acc[im][jn][0] + b0v, acc[im][jn][1] + b1v);
            float2 v1 = make_float2(acc[im][jn][2] + b0v, acc[im][jn][3] + b1v);
            *reinterpret_cast<float2*>(out + (size_t)r * N + c) = v0;
            *reinterpret_cast<float2*>(out + (size_t)(r + 8) * N + c) = v1;
        }
    }
}

// ---------------- host launch ------------------------------------------------
extern "C" void kernel_launch(void* const* d_in, const int* in_sizes, int n_in,
                              void* d_out, int out_size) {
    const float* x = (const float*)d_in[0];
    const float* w = (const float*)d_in[1];
    const float* b = (const float*)d_in[2];
    float* out = (float*)d_out;

    cudaFuncSetAttribute(gemm_kernel, cudaFuncAttributeMaxDynamicSharedMemorySize,
                         SMEM_TOTAL);

    prep_kernel<<<1024, 256>>>(x, w, b);

    dim3 grid(N / BN, M / BM);   // (16, 64)
    gemm_kernel<<<grid, NTHREADS, SMEM_TOTAL>>>(out);
}

// round 14
// speedup vs baseline: 2.8664x; 2.8664x over previous
#include <cuda_runtime.h>
#include <cuda_fp16.h>
#include <cstdint>

// ============================================================
// out[8192,4096] = x[8192,4096] @ sign(W)[4096,4096]^T + sign(b)
// Base-PTX tensor path: cp.async + ldmatrix + mma.sync.m16n8k16.f32.f16.
// R14: R12 (best) made PERSISTENT: grid=296 (2 CTA/SM), each CTA walks
//      tiles bid, bid+296, ... with ONE flat pipeline over all k-stages;
//      near tile boundaries the prefetch quarters already fetch the next
//      tile's first stages, so the cp.async ring never drains and the
//      epilogue overlaps the next tile's loads.
// ============================================================

static constexpr int M = 8192;
static constexpr int N = 4096;
static constexpr int K = 4096;

static constexpr int BM = 128;
static constexpr int BN = 128;
static constexpr int BK = 64;
static constexpr int KT = K / BK;          // 64 k-stages per tile
static constexpr int STAGES = 3;
static constexpr int NTHREADS = 128;

static constexpr int NTILES = (M / BM) * (N / BN);   // 2048
static constexpr int GRIDSZ = 296;                    // 2 CTAs/SM * 148 SMs

static constexpr int ROW_HALFS = BK + 8;   // 72 halves = 144B row (9x16B, conflict-free)
static constexpr int ROW_BYTES = ROW_HALFS * 2;              // 144
static constexpr int TILE_BYTES = BM * ROW_BYTES;            // 18432
static constexpr int STAGE_BYTES = 2 * TILE_BYTES;           // 36864 (A then B)
static constexpr int SMEM_TOTAL = STAGES * STAGE_BYTES;      // 110592

// ---------------- scratch (__device__ globals: alloc-free rule) ------------
__device__ __half g_xh[(size_t)M * K];   // fp16(x)
__device__ __half g_wh[(size_t)N * K];   // fp16(sign(W))
__device__ float  g_bs[N];               // sign(bias)

// ---------------- PTX helpers -----------------------------------------------
__device__ __forceinline__ uint32_t smem_u32(const void* p) {
    uint32_t a;
    asm("{ .reg .u64 t; cvta.to.shared.u64 t, %1; cvt.u32.u64 %0, t; }"
        : "=r"(a) : "l"(p));
    return a;
}

__device__ __forceinline__ void cp16(uint32_t s, const void* g) {
    asm volatile("cp.async.cg.shared.global [%0], [%1], 16;"
                 :: "r"(s), "l"(g) : "memory");
}
__device__ __forceinline__ void cp_commit() {
    asm volatile("cp.async.commit_group;" ::: "memory");
}
template <int NN>
__device__ __forceinline__ void cp_wait() {
    asm volatile("cp.async.wait_group %0;" :: "n"(NN) : "memory");
}

__device__ __forceinline__ void ldsm4(uint32_t* r, uint32_t addr) {
    asm volatile("ldmatrix.sync.aligned.m8n8.x4.shared.b16 {%0,%1,%2,%3}, [%4];"
                 : "=r"(r[0]), "=r"(r[1]), "=r"(r[2]), "=r"(r[3]) : "r"(addr));
}

__device__ __forceinline__ void mma16816(float* c, const uint32_t* a,
                                         uint32_t b0, uint32_t b1) {
    asm volatile(
        "mma.sync.aligned.m16n8k16.row.col.f32.f16.f16.f32 "
        "{%0,%1,%2,%3}, {%4,%5,%6,%7}, {%8,%9}, {%0,%1,%2,%3};"
        : "+f"(c[0]), "+f"(c[1]), "+f"(c[2]), "+f"(c[3])
        : "r"(a[0]), "r"(a[1]), "r"(a[2]), "r"(a[3]), "r"(b0), "r"(b1));
}

// ---------------- prep: fp32 -> fp16 / sign ---------------------------------
__device__ __forceinline__ float fsign(float v) {
    return (v > 0.f) ? 1.f : ((v < 0.f) ? -1.f : 0.f);
}

__global__ void prep_kernel(const float* __restrict__ x,
                            const float* __restrict__ w,
                            const float* __restrict__ b) {
    const long tid = (long)blockIdx.x * blockDim.x + threadIdx.x;
    const long stride = (long)gridDim.x * blockDim.x;
    const long NX4 = ((long)M * K) / 4;
    const long NW4 = ((long)N * K) / 4;

    __half2* xh2 = reinterpret_cast<__half2*>(g_xh);
    __half2* wh2 = reinterpret_cast<__half2*>(g_wh);

    for (long t = tid; t < NX4; t += stride) {
        float4 v = reinterpret_cast<const float4*>(x)[t];
        xh2[2 * t + 0] = __floats2half2_rn(v.x, v.y);
        xh2[2 * t + 1] = __floats2half2_rn(v.z, v.w);
    }
    for (long t = tid; t < NW4; t += stride) {
        float4 v = reinterpret_cast<const float4*>(w)[t];
        wh2[2 * t + 0] = __floats2half2_rn(fsign(v.x), fsign(v.y));
        wh2[2 * t + 1] = __floats2half2_rn(fsign(v.z), fsign(v.w));
    }
    if (tid < N) g_bs[tid] = fsign(b[tid]);
}

// ---------------- GEMM (persistent) ------------------------------------------
// grid = 296 1-D. 128 threads (4 warps: 2m x 2n), warp tile 64x64.
// Flat loop over s = 0..my_tiles*64-1; buffer = s%3 via rotating registers.
__global__ void __launch_bounds__(NTHREADS, 2)
gemm_kernel(float* __restrict__ out) {
    extern __shared__ __half smem[];
    const uint32_t sbase = smem_u32(smem);

    const int tid = threadIdx.x;
    const int wid = tid >> 5;
    const int lane = tid & 31;
    const int warp_m = wid & 1;         // 0..1
    const int warp_n = wid >> 1;        // 0..1

    const int bid = blockIdx.x;         // 0..295

    // anti-phase: co-resident pairs are ~(b, b+148); offset one of them so
    // the pair's barrier windows interleave instead of colliding.
    if ((bid / 148) & 1)
        asm volatile("nanosleep.u32 256;");

    // per-thread cp.async layout constants
    const int ld_row = tid >> 3;              // 0..15
    const int ld_kc  = tid & 7;               // 0..7 (16B chunk within row)
    const uint32_t s_off = ld_row * ROW_BYTES + ld_kc * 16;

    // ldmatrix per-lane bases
    const int rowA = warp_m * 64 + (lane & 15);
    const int kbA  = (lane >> 4) * 8;                        // halves
    const int rowB = warp_n * 64 + (lane & 7) + (lane >> 4) * 8;
    const int kbB  = ((lane >> 3) & 1) * 8;                  // halves

    const int my_tiles = (NTILES - 1 - bid) / GRIDSZ + 1;    // 6 or 7
    const int S_TOT = my_tiles * KT;

    // ---- issue-side tile state (pointers for stage s+2) ----
    int i_t = bid;
    const __half* giA;
    const __half* giB;
    int phase_i;
    auto set_issue_tile = [&](int t) {
        const int ibm = t >> 5, ibn = t & 31;
        giA = g_xh + (size_t)(ibm * BM + ld_row) * K + ld_kc * 8;
        giB = g_wh + (size_t)(ibn * BN + ld_row) * K + ld_kc * 8;
        phase_i = (t & 3) * (KT / 4);
    };
    set_issue_tile(i_t);

    // ---- consume-side tile state ----
    int c_t = bid;

    float acc[4][8][4];
    #pragma unroll
    for (int i = 0; i < 4; i++)
        #pragma unroll
        for (int j = 0; j < 8; j++)
            #pragma unroll
            for (int e = 0; e < 4; e++) acc[i][j][e] = 0.f;

    auto load_frags = [&](int stage, int kk, uint32_t (*a)[4], uint32_t (*b)[4]) {
        const uint32_t sA = sbase + stage * STAGE_BYTES;
        const uint32_t sB = sA + TILE_BYTES;
        #pragma unroll
        for (int im = 0; im < 4; im++)
            ldsm4(a[im], sA + (rowA + im * 16) * ROW_BYTES + (kbA + kk * 16) * 2);
        #pragma unroll
        for (int q = 0; q < 4; q++)
            ldsm4(b[q], sB + (rowB + q * 16) * ROW_BYTES + (kbB + kk * 16) * 2);
    };

    auto mma_half = [&](uint32_t (*a)[4], uint32_t (*b)[4]) {
        #pragma unroll
        for (int im = 0; im < 4; im++)
            #pragma unroll
            for (int jn = 0; jn < 8; jn++)
                mma16816(acc[im][jn],
                         a[im], b[jn >> 1][(jn & 1) * 2],
                                b[jn >> 1][(jn & 1) * 2 + 1]);
    };

    // full-stage issue (prologue only): 4 groups of 4 cp16 into buffer `stage`
    auto issue_full = [&](int stage) {
        const int kt = (stage + phase_i) & (KT - 1);
        const uint32_t sA = sbase + stage * STAGE_BYTES + s_off;
        const uint32_t sB = sA + TILE_BYTES;
        const __half* gA = giA + (size_t)kt * BK;
        const __half* gB = giB + (size_t)kt * BK;
        #pragma unroll
        for (int q = 0; q < 4; q++) {
            #pragma unroll
            for (int r = 0; r < 2; r++) {
                const int rg = q * 2 + r;
                cp16(sA + rg * (16 * ROW_BYTES), gA + (size_t)(rg * 16) * K);
                cp16(sB + rg * (16 * ROW_BYTES), gB + (size_t)(rg * 16) * K);
            }
            cp_commit();
        }
    };

    uint32_t a0[4][4], b0[4][4], a1[4][4], b1[4][4];

    // prologue: stages 0,1 of the first tile (8 quarter-groups);
    // cp_wait<4> -> stage 0 resident.
    issue_full(0);
    issue_full(1);
    cp_wait<4>();
    __syncthreads();
    load_frags(0, 0, a0, b0);

    // rotating buffer indices: stc=s%3, stn=(s+1)%3, st2=(s+2)%3
    int stc = 0, stn = 1, st2 = 2;

    for (int s = 0; s < S_TOT; s++) {
        const int j = s & (KT - 1);

        // advance issue-side tile when stage s+2 crosses a tile boundary
        if (j == KT - 2) {
            i_t += GRIDSZ;
            if (i_t < NTILES) set_issue_tile(i_t);
        }

        // hoisted stage-(s+2) addresses
        const bool pf = (s + 2 < S_TOT);
        const int ktI = (((j + 2) & (KT - 1)) + phase_i) & (KT - 1);
        const uint32_t sA2 = sbase + st2 * STAGE_BYTES + s_off;
        const uint32_t sB2 = sA2 + TILE_BYTES;
        const __half* gA2 = giA + (size_t)ktI * BK;
        const __half* gB2 = giB + (size_t)ktI * BK;

        #define ISSUE_Q(q)                                                    \
            do {                                                              \
                if (pf) {                                                     \
                    cp16(sA2 + (2*(q)+0) * (16 * ROW_BYTES),                  \
                         gA2 + (size_t)((2*(q)+0) * 16) * K);                 \
                    cp16(sB2 + (2*(q)+0) * (16 * ROW_BYTES),                  \
                         gB2 + (size_t)((2*(q)+0) * 16) * K);                 \
                    cp16(sA2 + (2*(q)+1) * (16 * ROW_BYTES),                  \
                         gA2 + (size_t)((2*(q)+1) * 16) * K);                 \
                    cp16(sB2 + (2*(q)+1) * (16 * ROW_BYTES),                  \
                         gB2 + (size_t)((2*(q)+1) * 16) * K);                 \
                }                                                             \
                cp_commit();                                                  \
            } while (0)

        load_frags(stc, 1, a1, b1);
        ISSUE_Q(0);
        mma_half(a0, b0);                   // kk=0

        load_frags(stc, 2, a0, b0);
        ISSUE_Q(1);
        mma_half(a1, b1);                   // kk=1

        load_frags(stc, 3, a1, b1);
        ISSUE_Q(2);
        mma_half(a0, b0);                   // kk=2

        ISSUE_Q(3);
        #undef ISSUE_Q
        // pending = 4 quarters of stage s+2 => stage s+1 resident;
        // barrier makes it visible + licenses buffer (s)%3 reuse.
        cp_wait<4>();
        __syncthreads();

        const int ldn = (s + 1 < S_TOT) ? stn : stc;
        load_frags(ldn, 0, a0, b0);         // next stage (possibly next tile)
        mma_half(a1, b1);                   // kk=3

        // ---------------- tile boundary: epilogue + reset -------------------
        if (j == KT - 1) {
            const int c_bm = c_t >> 5, c_bn = c_t & 31;
            const int col0 = c_bn * BN + warp_n * 64 + 2 * (lane & 3);
            const int row0 = c_bm * BM + warp_m * 64 + (lane >> 2);
            #pragma unroll
            for (int jn = 0; jn < 8; jn++) {
                const int c = col0 + jn * 8;
                const float b0v = g_bs[c];
                const float b1v = g_bs[c + 1];
                #pragma unroll
                for (int im = 0; im < 4; im++) {
                    const int r = row0 + im * 16;
                    float2 v0 = make_float2(acc[im][jn][0] + b0v,
                                            acc[im][jn][1] + b1v);
                    float2 v1 = make_float2(acc[im][jn][2] + b0v,
                                            acc[im][jn][3] + b1v);
                    *reinterpret_cast<float2*>(out + (size_t)r * N + c) = v0;
                    *reinterpret_cast<float2*>(out + (size_t)(r + 8) * N + c) = v1;
                }
            }
            #pragma unroll
            for (int i = 0; i < 4; i++)
                #pragma unroll
                for (int jj = 0; jj < 8; jj++)
                    #pragma unroll
                    for (int e = 0; e < 4; e++) acc[i][jj][e] = 0.f;
            c_t += GRIDSZ;
        }

        // rotate buffer indices
        const int tmp = stc; stc = stn; stn = st2; st2 = tmp;
    }
}

// ---------------- host launch ------------------------------------------------
extern "C" void kernel_launch(void* const* d_in, const int* in_sizes, int n_in,
                              void* d_out, int out_size) {
    const float* x = (const float*)d_in[0];
    const float* w = (const float*)d_in[1];
    const float* b = (const float*)d_in[2];
    float* out = (float*)d_out;

    cudaFuncSetAttribute(gemm_kernel, cudaFuncAttributeMaxDynamicSharedMemorySize,
                         SMEM_TOTAL);

    prep_kernel<<<1480, 256>>>(x, w, b);

    gemm_kernel<<<GRIDSZ, NTHREADS, SMEM_TOTAL>>>(out);
}

// round 15
// speedup vs baseline: 3.6290x; 1.2661x over previous
#include <cuda_runtime.h>
#include <cuda_fp16.h>
#include <cstdint>

// ============================================================
// out[8192,4096] = x[8192,4096] @ sign(W)[4096,4096]^T + sign(b)
// Base-PTX tensor path: cp.async + ldmatrix + mma.sync.m16n8k16.f32.f16.
// R15: R12 (best: 4-way LDGSTS spread, anti-phase, BK=64, 3 stages,
//      2 CTA/SM) with the k-loop EXPLICITLY UNROLLED BY 3 so all stage
//      indices are compile-time constants (R13/R14 showed dynamic state
//      + register pressure destroys the schedule; this removes it).
// ============================================================

static constexpr int M = 8192;
static constexpr int N = 4096;
static constexpr int K = 4096;

static constexpr int BM = 128;
static constexpr int BN = 128;
static constexpr int BK = 64;
static constexpr int KT = K / BK;          // 64 k-tiles
static constexpr int STAGES = 3;
static constexpr int NTHREADS = 128;

static constexpr int ROW_HALFS = BK + 8;   // 72 halves = 144B row (9x16B, conflict-free)
static constexpr int ROW_BYTES = ROW_HALFS * 2;              // 144
static constexpr int TILE_BYTES = BM * ROW_BYTES;            // 18432
static constexpr int STAGE_BYTES = 2 * TILE_BYTES;           // 36864 (A then B)
static constexpr int SMEM_TOTAL = STAGES * STAGE_BYTES;      // 110592

// ---------------- scratch (__device__ globals: alloc-free rule) ------------
__device__ __half g_xh[(size_t)M * K];   // fp16(x)
__device__ __half g_wh[(size_t)N * K];   // fp16(sign(W))
__device__ float  g_bs[N];               // sign(bias)

// ---------------- PTX helpers -----------------------------------------------
__device__ __forceinline__ uint32_t smem_u32(const void* p) {
    uint32_t a;
    asm("{ .reg .u64 t; cvta.to.shared.u64 t, %1; cvt.u32.u64 %0, t; }"
        : "=r"(a) : "l"(p));
    return a;
}

__device__ __forceinline__ void cp16(uint32_t s, const void* g) {
    asm volatile("cp.async.cg.shared.global [%0], [%1], 16;"
                 :: "r"(s), "l"(g) : "memory");
}
__device__ __forceinline__ void cp_commit() {
    asm volatile("cp.async.commit_group;" ::: "memory");
}
template <int NN>
__device__ __forceinline__ void cp_wait() {
    asm volatile("cp.async.wait_group %0;" :: "n"(NN) : "memory");
}

__device__ __forceinline__ void ldsm4(uint32_t* r, uint32_t addr) {
    asm volatile("ldmatrix.sync.aligned.m8n8.x4.shared.b16 {%0,%1,%2,%3}, [%4];"
                 : "=r"(r[0]), "=r"(r[1]), "=r"(r[2]), "=r"(r[3]) : "r"(addr));
}

__device__ __forceinline__ void mma16816(float* c, const uint32_t* a,
                                         uint32_t b0, uint32_t b1) {
    asm volatile(
        "mma.sync.aligned.m16n8k16.row.col.f32.f16.f16.f32 "
        "{%0,%1,%2,%3}, {%4,%5,%6,%7}, {%8,%9}, {%0,%1,%2,%3};"
        : "+f"(c[0]), "+f"(c[1]), "+f"(c[2]), "+f"(c[3])
        : "r"(a[0]), "r"(a[1]), "r"(a[2]), "r"(a[3]), "r"(b0), "r"(b1));
}

// ---------------- prep: fp32 -> fp16 / sign ---------------------------------
__device__ __forceinline__ float fsign(float v) {
    return (v > 0.f) ? 1.f : ((v < 0.f) ? -1.f : 0.f);
}

__global__ void prep_kernel(const float* __restrict__ x,
                            const float* __restrict__ w,
                            const float* __restrict__ b) {
    const long tid = (long)blockIdx.x * blockDim.x + threadIdx.x;
    const long stride = (long)gridDim.x * blockDim.x;
    const long NX4 = ((long)M * K) / 4;
    const long NW4 = ((long)N * K) / 4;

    __half2* xh2 = reinterpret_cast<__half2*>(g_xh);
    __half2* wh2 = reinterpret_cast<__half2*>(g_wh);

    for (long t = tid; t < NX4; t += stride) {
        float4 v = reinterpret_cast<const float4*>(x)[t];
        xh2[2 * t + 0] = __floats2half2_rn(v.x, v.y);
        xh2[2 * t + 1] = __floats2half2_rn(v.z, v.w);
    }
    for (long t = tid; t < NW4; t += stride) {
        float4 v = reinterpret_cast<const float4*>(w)[t];
        wh2[2 * t + 0] = __floats2half2_rn(fsign(v.x), fsign(v.y));
        wh2[2 * t + 1] = __floats2half2_rn(fsign(v.z), fsign(v.w));
    }
    if (tid < N) g_bs[tid] = fsign(b[tid]);
}

// ---------------- GEMM -------------------------------------------------------
// grid (N/BN=32, M/BM=64), 128 threads (4 warps: 2m x 2n), warp tile 64x64.
// 3-stage cp.async pipeline, 4 quarter-groups per stage, loop unrolled x3
// so stage indices are compile-time constants.
__global__ void __launch_bounds__(NTHREADS, 2)
gemm_kernel(float* __restrict__ out) {
    extern __shared__ __half smem[];
    const uint32_t sbase = smem_u32(smem);

    const int tid = threadIdx.x;
    const int wid = tid >> 5;
    const int lane = tid & 31;
    const int warp_m = wid & 1;         // 0..1
    const int warp_n = wid >> 1;        // 0..1

    const int bn = blockIdx.x;          // 0..31
    const int bm = blockIdx.y;          // 0..63
    const int bid = bm * gridDim.x + bn;
    const int phase = (bid & 3) * (KT / 4);   // spread L2 k-streams

    // anti-phase: co-resident pairs are ~(b, b+148); offset one of them so
    // the pair's barrier windows interleave instead of colliding.
    if ((bid / 148) & 1)
        asm volatile("nanosleep.u32 256;");

    // per-thread cp.async source pointers
    const int ld_row = tid >> 3;              // 0..15
    const int ld_kc  = tid & 7;               // 0..7 (16B chunk within row)
    const __half* gA_t = g_xh + (size_t)(bm * BM + ld_row) * K + ld_kc * 8;
    const __half* gB_t = g_wh + (size_t)(bn * BN + ld_row) * K + ld_kc * 8;
    const uint32_t s_off = ld_row * ROW_BYTES + ld_kc * 16;

    // ldmatrix per-lane bases
    const int rowA = warp_m * 64 + (lane & 15);
    const int kbA  = (lane >> 4) * 8;                        // halves
    const int rowB = warp_n * 64 + (lane & 7) + (lane >> 4) * 8;
    const int kbB  = ((lane >> 3) & 1) * 8;                  // halves

    float acc[4][8][4];
    #pragma unroll
    for (int i = 0; i < 4; i++)
        #pragma unroll
        for (int j = 0; j < 8; j++)
            #pragma unroll
            for (int e = 0; e < 4; e++) acc[i][j][e] = 0.f;

    auto load_frags = [&](int stage, int kk, uint32_t (*a)[4], uint32_t (*b)[4]) {
        const uint32_t sA = sbase + stage * STAGE_BYTES;
        const uint32_t sB = sA + TILE_BYTES;
        #pragma unroll
        for (int im = 0; im < 4; im++)
            ldsm4(a[im], sA + (rowA + im * 16) * ROW_BYTES + (kbA + kk * 16) * 2);
        #pragma unroll
        for (int q = 0; q < 4; q++)
            ldsm4(b[q], sB + (rowB + q * 16) * ROW_BYTES + (kbB + kk * 16) * 2);
    };

    auto mma_half = [&](uint32_t (*a)[4], uint32_t (*b)[4]) {
        #pragma unroll
        for (int im = 0; im < 4; im++)
            #pragma unroll
            for (int jn = 0; jn < 8; jn++)
                mma16816(acc[im][jn],
                         a[im], b[jn >> 1][(jn & 1) * 2],
                                b[jn >> 1][(jn & 1) * 2 + 1]);
    };

    // full-stage issue (prologue only): 4 groups of 4 cp16
    auto issue_full = [&](int j) {
        const int kt = (j + phase) & (KT - 1);
        const uint32_t sA = sbase + (j % STAGES) * STAGE_BYTES + s_off;
        const uint32_t sB = sA + TILE_BYTES;
        const __half* gA = gA_t + (size_t)kt * BK;
        const __half* gB = gB_t + (size_t)kt * BK;
        #pragma unroll
        for (int q = 0; q < 4; q++) {
            #pragma unroll
            for (int r = 0; r < 2; r++) {
                const int rg = q * 2 + r;
                cp16(sA + rg * (16 * ROW_BYTES), gA + (size_t)(rg * 16) * K);
                cp16(sB + rg * (16 * ROW_BYTES), gB + (size_t)(rg * 16) * K);
            }
            cp_commit();
        }
    };

    uint32_t a0[4][4], b0[4][4], a1[4][4], b1[4][4];

    // prologue: stages 0,1 issued as 4 quarters each (8 groups);
    // cp_wait<4> leaves <=4 pending (stage 1's quarters) => stage 0 resident.
    issue_full(0);
    issue_full(1);
    cp_wait<4>();
    __syncthreads();
    load_frags(0, 0, a0, b0);

    // quarter q of stage j+2 (constant stage offsets); always commits.
    #define ISSUE_Q(q)                                                        \
        do {                                                                  \
            if (pf) {                                                         \
                cp16(sA2 + (2*(q)+0) * (16 * ROW_BYTES),                      \
                     gA2 + (size_t)((2*(q)+0) * 16) * K);                     \
                cp16(sB2 + (2*(q)+0) * (16 * ROW_BYTES),                      \
                     gB2 + (size_t)((2*(q)+0) * 16) * K);                     \
                cp16(sA2 + (2*(q)+1) * (16 * ROW_BYTES),                      \
                     gA2 + (size_t)((2*(q)+1) * 16) * K);                     \
                cp16(sB2 + (2*(q)+1) * (16 * ROW_BYTES),                      \
                     gB2 + (size_t)((2*(q)+1) * 16) * K);                     \
            }                                                                 \
            cp_commit();                                                      \
        } while (0)

    // one k-iteration with compile-time stage indices STC/STN/ST2.
    // LDN = stage for the end-of-iteration kk0 preload (STN normally,
    // STC for the tail where there is no next stage).
    #define ITER(STC, STN, ST2, LDN)                                          \
        do {                                                                  \
            const bool pf = (j + 2 < KT);                                     \
            const int kt2 = ((j + 2 + phase) & (KT - 1));                     \
            const uint32_t sA2 = sbase + (ST2) * STAGE_BYTES + s_off;         \
            const uint32_t sB2 = sA2 + TILE_BYTES;                            \
            const __half* gA2 = gA_t + (size_t)kt2 * BK;                      \
            const __half* gB2 = gB_t + (size_t)kt2 * BK;                      \
            load_frags((STC), 1, a1, b1);                                     \
            ISSUE_Q(0);                                                       \
            mma_half(a0, b0);                 /* kk=0 */                      \
            load_frags((STC), 2, a0, b0);                                     \
            ISSUE_Q(1);                                                       \
            mma_half(a1, b1);                 /* kk=1 */                      \
            load_frags((STC), 3, a1, b1);                                     \
            ISSUE_Q(2);                                                       \
            mma_half(a0, b0);                 /* kk=2 */                      \
            ISSUE_Q(3);                                                       \
            cp_wait<4>();                     /* stage j+1 resident */        \
            __syncthreads();                  /* visible + buffer license */  \
            load_frags((LDN), 0, a0, b0);                                     \
            mma_half(a1, b1);                 /* kk=3 */                      \
            j++;                                                              \
        } while (0)

    int j = 0;
    #pragma unroll 1
    for (int blk = 0; blk < KT / 3; blk++) {   // 21 triples -> j = 0..62
        ITER(0, 1, 2, 1);
        ITER(1, 2, 0, 2);
        ITER(2, 0, 1, 0);
    }
    ITER(0, 1, 2, 0);                          // tail j=63 (pf=false)

    #undef ITER
    #undef ISSUE_Q

    // ---------------- epilogue: add sign(bias), store fp32 ------------------
    const int col0 = bn * BN + warp_n * 64 + 2 * (lane & 3);
    const int row0 = bm * BM + warp_m * 64 + (lane >> 2);
    #pragma unroll
    for (int jn = 0; jn < 8; jn++) {
        const int c = col0 + jn * 8;
        const float b0v = g_bs[c];
        const float b1v = g_bs[c + 1];
        #pragma unroll
        for (int im = 0; im < 4; im++) {
            const int r = row0 + im * 16;
            float2 v0 = make_float2(acc[im][jn][0] + b0v, acc[im][jn][1] + b1v);
            float2 v1 = make_float2(acc[im][jn][2] + b0v, acc[im][jn][3] + b1v);
            *reinterpret_cast<float2*>(out + (size_t)r * N + c) = v0;
            *reinterpret_cast<float2*>(out + (size_t)(r + 8) * N + c) = v1;
        }
    }
}

// ---------------- host launch ------------------------------------------------
extern "C" void kernel_launch(void* const* d_in, const int* in_sizes, int n_in,
                              void* d_out, int out_size) {
    const float* x = (const float*)d_in[0];
    const float* w = (const float*)d_in[1];
    const float* b = (const float*)d_in[2];
    float* out = (float*)d_out;

    cudaFuncSetAttribute(gemm_kernel, cudaFuncAttributeMaxDynamicSharedMemorySize,
                         SMEM_TOTAL);

    prep_kernel<<<1480, 256>>>(x, w, b);

    dim3 grid(N / BN, M / BM);   // (32, 64)
    gemm_kernel<<<grid, NTHREADS, SMEM_TOTAL>>>(out);
}

// round 16
// speedup vs baseline: 3.6582x; 1.0080x over previous
#include <cuda_runtime.h>
#include <cuda_fp16.h>
#include <cstdint>

// ============================================================
// out[8192,4096] = x[8192,4096] @ sign(W)[4096,4096]^T + sign(b)
// Base-PTX tensor path: cp.async + ldmatrix + mma.sync.m16n8k16.f32.f16.
// R16: R15 GEMM (k-loop unrolled x3, const stage indices -- measured
//      best GEMM: 513.3us) + R12's prep launch config <<<1024,256>>>
//      (measured best prep: 41.7us). One-variable recombination.
// ============================================================

static constexpr int M = 8192;
static constexpr int N = 4096;
static constexpr int K = 4096;

static constexpr int BM = 128;
static constexpr int BN = 128;
static constexpr int BK = 64;
static constexpr int KT = K / BK;          // 64 k-tiles
static constexpr int STAGES = 3;
static constexpr int NTHREADS = 128;

static constexpr int ROW_HALFS = BK + 8;   // 72 halves = 144B row (9x16B, conflict-free)
static constexpr int ROW_BYTES = ROW_HALFS * 2;              // 144
static constexpr int TILE_BYTES = BM * ROW_BYTES;            // 18432
static constexpr int STAGE_BYTES = 2 * TILE_BYTES;           // 36864 (A then B)
static constexpr int SMEM_TOTAL = STAGES * STAGE_BYTES;      // 110592

// ---------------- scratch (__device__ globals: alloc-free rule) ------------
__device__ __half g_xh[(size_t)M * K];   // fp16(x)
__device__ __half g_wh[(size_t)N * K];   // fp16(sign(W))
__device__ float  g_bs[N];               // sign(bias)

// ---------------- PTX helpers -----------------------------------------------
__device__ __forceinline__ uint32_t smem_u32(const void* p) {
    uint32_t a;
    asm("{ .reg .u64 t; cvta.to.shared.u64 t, %1; cvt.u32.u64 %0, t; }"
        : "=r"(a) : "l"(p));
    return a;
}

__device__ __forceinline__ void cp16(uint32_t s, const void* g) {
    asm volatile("cp.async.cg.shared.global [%0], [%1], 16;"
                 :: "r"(s), "l"(g) : "memory");
}
__device__ __forceinline__ void cp_commit() {
    asm volatile("cp.async.commit_group;" ::: "memory");
}
template <int NN>
__device__ __forceinline__ void cp_wait() {
    asm volatile("cp.async.wait_group %0;" :: "n"(NN) : "memory");
}

__device__ __forceinline__ void ldsm4(uint32_t* r, uint32_t addr) {
    asm volatile("ldmatrix.sync.aligned.m8n8.x4.shared.b16 {%0,%1,%2,%3}, [%4];"
                 : "=r"(r[0]), "=r"(r[1]), "=r"(r[2]), "=r"(r[3]) : "r"(addr));
}

__device__ __forceinline__ void mma16816(float* c, const uint32_t* a,
                                         uint32_t b0, uint32_t b1) {
    asm volatile(
        "mma.sync.aligned.m16n8k16.row.col.f32.f16.f16.f32 "
        "{%0,%1,%2,%3}, {%4,%5,%6,%7}, {%8,%9}, {%0,%1,%2,%3};"
        : "+f"(c[0]), "+f"(c[1]), "+f"(c[2]), "+f"(c[3])
        : "r"(a[0]), "r"(a[1]), "r"(a[2]), "r"(a[3]), "r"(b0), "r"(b1));
}

// ---------------- prep: fp32 -> fp16 / sign ---------------------------------
__device__ __forceinline__ float fsign(float v) {
    return (v > 0.f) ? 1.f : ((v < 0.f) ? -1.f : 0.f);
}

__global__ void prep_kernel(const float* __restrict__ x,
                            const float* __restrict__ w,
                            const float* __restrict__ b) {
    const long tid = (long)blockIdx.x * blockDim.x + threadIdx.x;
    const long stride = (long)gridDim.x * blockDim.x;
    const long NX4 = ((long)M * K) / 4;
    const long NW4 = ((long)N * K) / 4;

    __half2* xh2 = reinterpret_cast<__half2*>(g_xh);
    __half2* wh2 = reinterpret_cast<__half2*>(g_wh);

    for (long t = tid; t < NX4; t += stride) {
        float4 v = reinterpret_cast<const float4*>(x)[t];
        xh2[2 * t + 0] = __floats2half2_rn(v.x, v.y);
        xh2[2 * t + 1] = __floats2half2_rn(v.z, v.w);
    }
    for (long t = tid; t < NW4; t += stride) {
        float4 v = reinterpret_cast<const float4*>(w)[t];
        wh2[2 * t + 0] = __floats2half2_rn(fsign(v.x), fsign(v.y));
        wh2[2 * t + 1] = __floats2half2_rn(fsign(v.z), fsign(v.w));
    }
    if (tid < N) g_bs[tid] = fsign(b[tid]);
}

// ---------------- GEMM -------------------------------------------------------
// grid (N/BN=32, M/BM=64), 128 threads (4 warps: 2m x 2n), warp tile 64x64.
// 3-stage cp.async pipeline, 4 quarter-groups per stage, loop unrolled x3
// so stage indices are compile-time constants.
__global__ void __launch_bounds__(NTHREADS, 2)
gemm_kernel(float* __restrict__ out) {
    extern __shared__ __half smem[];
    const uint32_t sbase = smem_u32(smem);

    const int tid = threadIdx.x;
    const int wid = tid >> 5;
    const int lane = tid & 31;
    const int warp_m = wid & 1;         // 0..1
    const int warp_n = wid >> 1;        // 0..1

    const int bn = blockIdx.x;          // 0..31
    const int bm = blockIdx.y;          // 0..63
    const int bid = bm * gridDim.x + bn;
    const int phase = (bid & 3) * (KT / 4);   // spread L2 k-streams

    // anti-phase: co-resident pairs are ~(b, b+148); offset one of them so
    // the pair's barrier windows interleave instead of colliding.
    if ((bid / 148) & 1)
        asm volatile("nanosleep.u32 256;");

    // per-thread cp.async source pointers
    const int ld_row = tid >> 3;              // 0..15
    const int ld_kc  = tid & 7;               // 0..7 (16B chunk within row)
    const __half* gA_t = g_xh + (size_t)(bm * BM + ld_row) * K + ld_kc * 8;
    const __half* gB_t = g_wh + (size_t)(bn * BN + ld_row) * K + ld_kc * 8;
    const uint32_t s_off = ld_row * ROW_BYTES + ld_kc * 16;

    // ldmatrix per-lane bases
    const int rowA = warp_m * 64 + (lane & 15);
    const int kbA  = (lane >> 4) * 8;                        // halves
    const int rowB = warp_n * 64 + (lane & 7) + (lane >> 4) * 8;
    const int kbB  = ((lane >> 3) & 1) * 8;                  // halves

    float acc[4][8][4];
    #pragma unroll
    for (int i = 0; i < 4; i++)
        #pragma unroll
        for (int j = 0; j < 8; j++)
            #pragma unroll
            for (int e = 0; e < 4; e++) acc[i][j][e] = 0.f;

    auto load_frags = [&](int stage, int kk, uint32_t (*a)[4], uint32_t (*b)[4]) {
        const uint32_t sA = sbase + stage * STAGE_BYTES;
        const uint32_t sB = sA + TILE_BYTES;
        #pragma unroll
        for (int im = 0; im < 4; im++)
            ldsm4(a[im], sA + (rowA + im * 16) * ROW_BYTES + (kbA + kk * 16) * 2);
        #pragma unroll
        for (int q = 0; q < 4; q++)
            ldsm4(b[q], sB + (rowB + q * 16) * ROW_BYTES + (kbB + kk * 16) * 2);
    };

    auto mma_half = [&](uint32_t (*a)[4], uint32_t (*b)[4]) {
        #pragma unroll
        for (int im = 0; im < 4; im++)
            #pragma unroll
            for (int jn = 0; jn < 8; jn++)
                mma16816(acc[im][jn],
                         a[im], b[jn >> 1][(jn & 1) * 2],
                                b[jn >> 1][(jn & 1) * 2 + 1]);
    };

    // full-stage issue (prologue only): 4 groups of 4 cp16
    auto issue_full = [&](int j) {
        const int kt = (j + phase) & (KT - 1);
        const uint32_t sA = sbase + (j % STAGES) * STAGE_BYTES + s_off;
        const uint32_t sB = sA + TILE_BYTES;
        const __half* gA = gA_t + (size_t)kt * BK;
        const __half* gB = gB_t + (size_t)kt * BK;
        #pragma unroll
        for (int q = 0; q < 4; q++) {
            #pragma unroll
            for (int r = 0; r < 2; r++) {
                const int rg = q * 2 + r;
                cp16(sA + rg * (16 * ROW_BYTES), gA + (size_t)(rg * 16) * K);
                cp16(sB + rg * (16 * ROW_BYTES), gB + (size_t)(rg * 16) * K);
            }
            cp_commit();
        }
    };

    uint32_t a0[4][4], b0[4][4], a1[4][4], b1[4][4];

    // prologue: stages 0,1 issued as 4 quarters each (8 groups);
    // cp_wait<4> leaves <=4 pending (stage 1's quarters) => stage 0 resident.
    issue_full(0);
    issue_full(1);
    cp_wait<4>();
    __syncthreads();
    load_frags(0, 0, a0, b0);

    // quarter q of stage j+2 (constant stage offsets); always commits.
    #define ISSUE_Q(q)                                                        \
        do {                                                                  \
            if (pf) {                                                         \
                cp16(sA2 + (2*(q)+0) * (16 * ROW_BYTES),                      \
                     gA2 + (size_t)((2*(q)+0) * 16) * K);                     \
                cp16(sB2 + (2*(q)+0) * (16 * ROW_BYTES),                      \
                     gB2 + (size_t)((2*(q)+0) * 16) * K);                     \
                cp16(sA2 + (2*(q)+1) * (16 * ROW_BYTES),                      \
                     gA2 + (size_t)((2*(q)+1) * 16) * K);                     \
                cp16(sB2 + (2*(q)+1) * (16 * ROW_BYTES),                      \
                     gB2 + (size_t)((2*(q)+1) * 16) * K);                     \
            }                                                                 \
            cp_commit();                                                      \
        } while (0)

    // one k-iteration with compile-time stage indices STC/STN/ST2.
    // LDN = stage for the end-of-iteration kk0 preload (STN normally,
    // STC for the tail where there is no next stage).
    #define ITER(STC, STN, ST2, LDN)                                          \
        do {                                                                  \
            const bool pf = (j + 2 < KT);                                     \
            const int kt2 = ((j + 2 + phase) & (KT - 1));                     \
            const uint32_t sA2 = sbase + (ST2) * STAGE_BYTES + s_off;         \
            const uint32_t sB2 = sA2 + TILE_BYTES;                            \
            const __half* gA2 = gA_t + (size_t)kt2 * BK;                      \
            const __half* gB2 = gB_t + (size_t)kt2 * BK;                      \
            load_frags((STC), 1, a1, b1);                                     \
            ISSUE_Q(0);                                                       \
            mma_half(a0, b0);                 /* kk=0 */                      \
            load_frags((STC), 2, a0, b0);                                     \
            ISSUE_Q(1);                                                       \
            mma_half(a1, b1);                 /* kk=1 */                      \
            load_frags((STC), 3, a1, b1);                                     \
            ISSUE_Q(2);                                                       \
            mma_half(a0, b0);                 /* kk=2 */                      \
            ISSUE_Q(3);                                                       \
            cp_wait<4>();                     /* stage j+1 resident */        \
            __syncthreads();                  /* visible + buffer license */  \
            load_frags((LDN), 0, a0, b0);                                     \
            mma_half(a1, b1);                 /* kk=3 */                      \
            j++;                                                              \
        } while (0)

    int j = 0;
    #pragma unroll 1
    for (int blk = 0; blk < KT / 3; blk++) {   // 21 triples -> j = 0..62
        ITER(0, 1, 2, 1);
        ITER(1, 2, 0, 2);
        ITER(2, 0, 1, 0);
    }
    ITER(0, 1, 2, 0);                          // tail j=63 (pf=false)

    #undef ITER
    #undef ISSUE_Q

    // ---------------- epilogue: add sign(bias), store fp32 ------------------
    const int col0 = bn * BN + warp_n * 64 + 2 * (lane & 3);
    const int row0 = bm * BM + warp_m * 64 + (lane >> 2);
    #pragma unroll
    for (int jn = 0; jn < 8; jn++) {
        const int c = col0 + jn * 8;
        const float b0v = g_bs[c];
        const float b1v = g_bs[c + 1];
        #pragma unroll
        for (int im = 0; im < 4; im++) {
            const int r = row0 + im * 16;
            float2 v0 = make_float2(acc[im][jn][0] + b0v, acc[im][jn][1] + b1v);
            float2 v1 = make_float2(acc[im][jn][2] + b0v, acc[im][jn][3] + b1v);
            *reinterpret_cast<float2*>(out + (size_t)r * N + c) = v0;
            *reinterpret_cast<float2*>(out + (size_t)(r + 8) * N + c) = v1;
        }
    }
}

// ---------------- host launch ------------------------------------------------
extern "C" void kernel_launch(void* const* d_in, const int* in_sizes, int n_in,
                              void* d_out, int out_size) {
    const float* x = (const float*)d_in[0];
    const float* w = (const float*)d_in[1];
    const float* b = (const float*)d_in[2];
    float* out = (float*)d_out;

    cudaFuncSetAttribute(gemm_kernel, cudaFuncAttributeMaxDynamicSharedMemorySize,
                         SMEM_TOTAL);

    prep_kernel<<<1024, 256>>>(x, w, b);

    dim3 grid(N / BN, M / BM);   // (32, 64)
    gemm_kernel<<<grid, NTHREADS, SMEM_TOTAL>>>(out);
}